// round 1
// baseline (speedup 1.0000x reference)
#include <cuda_runtime.h>
#include <cstdint>

// ---------------------------------------------------------------------------
// Instant-NGP HashEncoder: B=2,097,152 points, D=3, L=16 levels, C=2 features,
// base_res=16, desired=2048, log2_hashmap=19.
//
// Compile-time level config (verified: total params == 6,098,120 matches ref):
//   res:      16,23,31,43,59,81,112,154,213,295,407,562,777,1073,1483,2048
//   dense for levels 0..4 (res^3 <= aligned hashmap), hashed for 5..15
//   hashed levels all have exactly 2^19 = 524288 entries -> idx & 0x7FFFF
// ---------------------------------------------------------------------------

#define NLEVELS 16
#define HASH_MASK 524287u
#define P2 2654435761u
#define P3 805459861u

__device__ float g_scales[NLEVELS];

__global__ void init_scales_kernel() {
    int l = threadIdx.x;
    if (l < NLEVELS) {
        // match numpy: scale = exp2(l * log2(128)/15) * 16 - 1  (float64 -> float32)
        double s = exp2((double)l * (7.0 / 15.0)) * 16.0 - 1.0;
        g_scales[l] = (float)s;
    }
}

__global__ __launch_bounds__(256)
void hash_encode_kernel(const float* __restrict__ inputs,
                        const float2* __restrict__ emb,
                        float* __restrict__ out,
                        int B)
{
    const int b = blockIdx.x * blockDim.x + threadIdx.x;
    if (b >= B) return;

    const float x = __ldg(&inputs[b * 3 + 0]);
    const float y = __ldg(&inputs[b * 3 + 1]);
    const float z = __ldg(&inputs[b * 3 + 2]);

    // compile-time level tables
    constexpr unsigned RES_[NLEVELS] = {16u, 23u, 31u, 43u, 59u, 81u, 112u, 154u,
                                        213u, 295u, 407u, 562u, 777u, 1073u, 1483u, 2048u};
    constexpr unsigned OFF_[NLEVELS] = {0u, 4096u, 16264u, 46056u, 125568u,
                                        330952u, 855240u, 1379528u, 1903816u,
                                        2428104u, 2952392u, 3476680u, 4000968u,
                                        4525256u, 5049544u, 5573832u};
    // level >= 5 hashed

    float acc[2 * NLEVELS];

#pragma unroll
    for (int l = 0; l < NLEVELS; ++l) {
        const float scale = g_scales[l];
        const unsigned res = RES_[l];
        const unsigned rm1 = res - 1u;

        // pos = x*scale + 0.5 (separate mul/add to track reference rounding)
        const float px = __fadd_rn(__fmul_rn(x, scale), 0.5f);
        const float py = __fadd_rn(__fmul_rn(y, scale), 0.5f);
        const float pz = __fadd_rn(__fmul_rn(z, scale), 0.5f);

        const float fxg = floorf(px), fyg = floorf(py), fzg = floorf(pz);
        const float fx = px - fxg, fy = py - fyg, fz = pz - fzg;
        const unsigned gx = (unsigned)fxg, gy = (unsigned)fyg, gz = (unsigned)fzg;

        const float wx[2] = {1.0f - fx, fx};
        const float wy[2] = {1.0f - fy, fy};
        const float wz[2] = {1.0f - fz, fz};

        // clamped corner coords (shared between corners)
        const unsigned cx0 = min(gx, rm1), cx1 = min(gx + 1u, rm1);
        const unsigned cy0 = min(gy, rm1), cy1 = min(gy + 1u, rm1);
        const unsigned cz0 = min(gz, rm1), cz1 = min(gz + 1u, rm1);

        const float2* __restrict__ tab = emb + OFF_[l];

        float ax = 0.0f, ay = 0.0f;

        if (l >= 5) {
            // hashed level: idx = (cx ^ cy*P2 ^ cz*P3) & MASK
            const unsigned hy0 = cy0 * P2, hy1 = cy1 * P2;
            const unsigned hz0 = cz0 * P3, hz1 = cz1 * P3;
#pragma unroll
            for (int c = 0; c < 8; ++c) {
                const unsigned bx = c & 1u, by = (c >> 1) & 1u, bz = (c >> 2) & 1u;
                const unsigned cx = bx ? cx1 : cx0;
                const unsigned hy = by ? hy1 : hy0;
                const unsigned hz = bz ? hz1 : hz0;
                const unsigned idx = (cx ^ hy ^ hz) & HASH_MASK;
                const float2 e = __ldg(tab + idx);
                const float w = wx[bx] * wy[by] * wz[bz];
                ax = fmaf(w, e.x, ax);
                ay = fmaf(w, e.y, ay);
            }
        } else {
            // dense level: idx = cx + cy*res + cz*res^2
            const unsigned ry0 = cy0 * res, ry1 = cy1 * res;
            const unsigned rz0 = cz0 * res * res, rz1 = cz1 * res * res;
#pragma unroll
            for (int c = 0; c < 8; ++c) {
                const unsigned bx = c & 1u, by = (c >> 1) & 1u, bz = (c >> 2) & 1u;
                const unsigned cx = bx ? cx1 : cx0;
                const unsigned ry = by ? ry1 : ry0;
                const unsigned rz = bz ? rz1 : rz0;
                const unsigned idx = cx + ry + rz;
                const float2 e = __ldg(tab + idx);
                const float w = wx[bx] * wy[by] * wz[bz];
                ax = fmaf(w, e.x, ax);
                ay = fmaf(w, e.y, ay);
            }
        }

        acc[2 * l + 0] = ax;
        acc[2 * l + 1] = ay;
    }

    // coalesced-ish output: 32 contiguous floats per point, 8x float4 stores
    float4* __restrict__ o4 = reinterpret_cast<float4*>(out + (size_t)b * (2 * NLEVELS));
#pragma unroll
    for (int i = 0; i < 8; ++i) {
        o4[i] = make_float4(acc[4 * i + 0], acc[4 * i + 1],
                            acc[4 * i + 2], acc[4 * i + 3]);
    }
}

extern "C" void kernel_launch(void* const* d_in, const int* in_sizes, int n_in,
                              void* d_out, int out_size) {
    const float*  inputs = (const float*)d_in[0];        // [B, 3]
    const float2* emb    = (const float2*)d_in[1];       // [TOTAL_PARAMS, 2] as float2
    float*        out    = (float*)d_out;                // [B, 32]

    const int B = in_sizes[0] / 3;

    init_scales_kernel<<<1, 32>>>();

    const int threads = 256;
    const int blocks = (B + threads - 1) / threads;
    hash_encode_kernel<<<blocks, threads>>>(inputs, emb, out, B);
}

// round 3
// speedup vs baseline: 1.0750x; 1.0750x over previous
#include <cuda_runtime.h>
#include <cstdint>

// ---------------------------------------------------------------------------
// Instant-NGP HashEncoder: B=2,097,152 points, D=3, L=16 levels, C=2 features,
// base_res=16, desired=2048, log2_hashmap=19.
//
// R2: x-corner pair merging (LDG.128 when the two x-corners of a cell are
// adjacent + 16B-aligned) to cut l1tex wavefronts ~25%; interleaved float4
// output stores + launch_bounds to raise occupancy.
// ---------------------------------------------------------------------------

#define NLEVELS 16
#define HASH_MASK 524287u
#define P2 2654435761u
#define P3 805459861u

__device__ float g_scales[NLEVELS];

__global__ void init_scales_kernel() {
    int l = threadIdx.x;
    if (l < NLEVELS) {
        // match numpy: scale = exp2(l * log2(128)/15) * 16 - 1  (float64 -> float32)
        double s = exp2((double)l * (7.0 / 15.0)) * 16.0 - 1.0;
        g_scales[l] = (float)s;
    }
}

__global__ __launch_bounds__(256, 5)
void hash_encode_kernel(const float* __restrict__ inputs,
                        const float2* __restrict__ emb,
                        float* __restrict__ out,
                        int B)
{
    const int b = blockIdx.x * blockDim.x + threadIdx.x;
    if (b >= B) return;

    const float x = __ldg(&inputs[b * 3 + 0]);
    const float y = __ldg(&inputs[b * 3 + 1]);
    const float z = __ldg(&inputs[b * 3 + 2]);

    constexpr unsigned RES_[NLEVELS] = {16u, 23u, 31u, 43u, 59u, 81u, 112u, 154u,
                                        213u, 295u, 407u, 562u, 777u, 1073u, 1483u, 2048u};
    constexpr unsigned OFF_[NLEVELS] = {0u, 4096u, 16264u, 46056u, 125568u,
                                        330952u, 855240u, 1379528u, 1903816u,
                                        2428104u, 2952392u, 3476680u, 4000968u,
                                        4525256u, 5049544u, 5573832u};
    // levels 0..4 dense, 5..15 hashed (hashmap exactly 2^19)

    float4* __restrict__ o4 = reinterpret_cast<float4*>(out + (size_t)b * (2 * NLEVELS));

    float prevx = 0.0f, prevy = 0.0f;

#pragma unroll
    for (int l = 0; l < NLEVELS; ++l) {
        const float scale = g_scales[l];
        const unsigned res = RES_[l];
        const unsigned rm1 = res - 1u;

        const float px = __fadd_rn(__fmul_rn(x, scale), 0.5f);
        const float py = __fadd_rn(__fmul_rn(y, scale), 0.5f);
        const float pz = __fadd_rn(__fmul_rn(z, scale), 0.5f);

        const float fxg = floorf(px), fyg = floorf(py), fzg = floorf(pz);
        const float fx = px - fxg, fy = py - fyg, fz = pz - fzg;
        const unsigned gx = (unsigned)fxg, gy = (unsigned)fyg, gz = (unsigned)fzg;

        const float wx0 = 1.0f - fx, wx1 = fx;
        const float wy_[2] = {1.0f - fy, fy};
        const float wz_[2] = {1.0f - fz, fz};

        const unsigned cx0 = min(gx, rm1), cx1 = min(gx + 1u, rm1);
        const unsigned cy0 = min(gy, rm1), cy1 = min(gy + 1u, rm1);
        const unsigned cz0 = min(gz, rm1), cz1 = min(gz + 1u, rm1);

        const float2* __restrict__ tab = emb + OFF_[l];
        const float4* __restrict__ tab4 = reinterpret_cast<const float4*>(tab);

        float ax = 0.0f, ay = 0.0f;

        // per-(y,z) base term: dense -> additive offset; hashed -> xor term
        unsigned byz[4];
        if (l >= 5) {
            const unsigned hy0 = cy0 * P2, hy1 = cy1 * P2;
            const unsigned hz0 = cz0 * P3, hz1 = cz1 * P3;
            byz[0] = hy0 ^ hz0; byz[1] = hy1 ^ hz0;
            byz[2] = hy0 ^ hz1; byz[3] = hy1 ^ hz1;
        } else {
            const unsigned ry0 = cy0 * res, ry1 = cy1 * res;
            const unsigned rz0 = cz0 * res * res, rz1 = cz1 * res * res;
            byz[0] = ry0 + rz0; byz[1] = ry1 + rz0;
            byz[2] = ry0 + rz1; byz[3] = ry1 + rz1;
        }

#pragma unroll
        for (int p = 0; p < 4; ++p) {
            const unsigned by = p & 1u, bz = (p >> 1) & 1u;
            const float wyz = wy_[by] * wz_[bz];
            const float w0 = wx0 * wyz, w1 = wx1 * wyz;

            unsigned i0, i1;
            if (l >= 5) {
                i0 = (cx0 ^ byz[p]) & HASH_MASK;
                i1 = (cx1 ^ byz[p]) & HASH_MASK;
            } else {
                i0 = cx0 + byz[p];
                i1 = cx1 + byz[p];
            }

            if ((i1 == i0 + 1u) && !(i0 & 1u)) {
                // both corners in one aligned 16B chunk -> single LDG.128
                const float4 q = __ldg(tab4 + (i0 >> 1));
                ax = fmaf(w0, q.x, ax);
                ay = fmaf(w0, q.y, ay);
                ax = fmaf(w1, q.z, ax);
                ay = fmaf(w1, q.w, ay);
            } else {
                const float2 e0 = __ldg(tab + i0);
                const float2 e1 = __ldg(tab + i1);
                ax = fmaf(w0, e0.x, ax);
                ay = fmaf(w0, e0.y, ay);
                ax = fmaf(w1, e1.x, ax);
                ay = fmaf(w1, e1.y, ay);
            }
        }

        // interleaved store: one float4 per pair of levels (short live ranges)
        if (l & 1) {
            o4[l >> 1] = make_float4(prevx, prevy, ax, ay);
        } else {
            prevx = ax;
            prevy = ay;
        }
    }
}

extern "C" void kernel_launch(void* const* d_in, const int* in_sizes, int n_in,
                              void* d_out, int out_size) {
    const float*  inputs = (const float*)d_in[0];   // [B, 3]
    const float2* emb    = (const float2*)d_in[1];  // [TOTAL_PARAMS, 2]
    float*        out    = (float*)d_out;           // [B, 32]

    const int B = in_sizes[0] / 3;

    init_scales_kernel<<<1, 32>>>();

    const int threads = 256;
    const int blocks = (B + threads - 1) / threads;
    hash_encode_kernel<<<blocks, threads>>>(inputs, emb, out, B);
}

// round 4
// speedup vs baseline: 1.2163x; 1.1315x over previous
#include <cuda_runtime.h>
#include <cstdint>

// ---------------------------------------------------------------------------
// Instant-NGP HashEncoder: B=2,097,152 points, D=3, L=16, C=2,
// base_res=16, desired=2048, log2_hashmap=19.
//
// R3: 8 threads per point, each thread computes 2 consecutive levels and
// writes exactly one float4 of the 128B output row -> fully coalesced stores
// (store wavefronts 8/point -> 1/point). Keeps x-pair LDG.128 merging.
// ---------------------------------------------------------------------------

#define NLEVELS 16
#define HASH_MASK 524287u
#define P2 2654435761u
#define P3 805459861u

// level tables (verified: total params == 6,098,120 matches reference)
__device__ const unsigned g_res[NLEVELS] = {16u, 23u, 31u, 43u, 59u, 81u, 112u, 154u,
                                            213u, 295u, 407u, 562u, 777u, 1073u, 1483u, 2048u};
__device__ const unsigned g_off[NLEVELS] = {0u, 4096u, 16264u, 46056u, 125568u,
                                            330952u, 855240u, 1379528u, 1903816u,
                                            2428104u, 2952392u, 3476680u, 4000968u,
                                            4525256u, 5049544u, 5573832u};
__device__ float g_scales[NLEVELS];

__global__ void init_scales_kernel() {
    int l = threadIdx.x;
    if (l < NLEVELS) {
        // match numpy: scale = exp2(l * log2(128)/15) * 16 - 1  (float64 -> float32)
        double s = exp2((double)l * (7.0 / 15.0)) * 16.0 - 1.0;
        g_scales[l] = (float)s;
    }
}

__device__ __forceinline__ void encode_level(int l, float x, float y, float z,
                                             const float2* __restrict__ emb,
                                             float& ax, float& ay)
{
    const float scale = g_scales[l];
    const unsigned res = __ldg(&g_res[l]);
    const unsigned rm1 = res - 1u;
    const unsigned off = __ldg(&g_off[l]);

    const float px = __fadd_rn(__fmul_rn(x, scale), 0.5f);
    const float py = __fadd_rn(__fmul_rn(y, scale), 0.5f);
    const float pz = __fadd_rn(__fmul_rn(z, scale), 0.5f);

    const float fxg = floorf(px), fyg = floorf(py), fzg = floorf(pz);
    const float fx = px - fxg, fy = py - fyg, fz = pz - fzg;
    const unsigned gx = (unsigned)fxg, gy = (unsigned)fyg, gz = (unsigned)fzg;

    const float wx0 = 1.0f - fx, wx1 = fx;
    const float wy_[2] = {1.0f - fy, fy};
    const float wz_[2] = {1.0f - fz, fz};

    const unsigned cx0 = min(gx, rm1), cx1 = min(gx + 1u, rm1);
    const unsigned cy0 = min(gy, rm1), cy1 = min(gy + 1u, rm1);
    const unsigned cz0 = min(gz, rm1), cz1 = min(gz + 1u, rm1);

    const float2* __restrict__ tab = emb + off;
    const float4* __restrict__ tab4 = reinterpret_cast<const float4*>(tab);

    // per-(y,z) index bases and the two x-corner indices
    unsigned i0a[4], i1a[4];
    if (l >= 5) {
        const unsigned hy0 = cy0 * P2, hy1 = cy1 * P2;
        const unsigned hz0 = cz0 * P3, hz1 = cz1 * P3;
        const unsigned b0 = hy0 ^ hz0, b1 = hy1 ^ hz0, b2 = hy0 ^ hz1, b3 = hy1 ^ hz1;
        i0a[0] = (cx0 ^ b0) & HASH_MASK; i1a[0] = (cx1 ^ b0) & HASH_MASK;
        i0a[1] = (cx0 ^ b1) & HASH_MASK; i1a[1] = (cx1 ^ b1) & HASH_MASK;
        i0a[2] = (cx0 ^ b2) & HASH_MASK; i1a[2] = (cx1 ^ b2) & HASH_MASK;
        i0a[3] = (cx0 ^ b3) & HASH_MASK; i1a[3] = (cx1 ^ b3) & HASH_MASK;
    } else {
        const unsigned ry0 = cy0 * res, ry1 = cy1 * res;
        const unsigned rz0 = cz0 * res * res, rz1 = cz1 * res * res;
        const unsigned b0 = ry0 + rz0, b1 = ry1 + rz0, b2 = ry0 + rz1, b3 = ry1 + rz1;
        i0a[0] = cx0 + b0; i1a[0] = cx1 + b0;
        i0a[1] = cx0 + b1; i1a[1] = cx1 + b1;
        i0a[2] = cx0 + b2; i1a[2] = cx1 + b2;
        i0a[3] = cx0 + b3; i1a[3] = cx1 + b3;
    }

    ax = 0.0f; ay = 0.0f;
#pragma unroll
    for (int p = 0; p < 4; ++p) {
        const unsigned by = p & 1u, bz = (p >> 1) & 1u;
        const float wyz = wy_[by] * wz_[bz];
        const float w0 = wx0 * wyz, w1 = wx1 * wyz;
        const unsigned i0 = i0a[p], i1 = i1a[p];

        if ((i1 == i0 + 1u) && !(i0 & 1u)) {
            // both x-corners in one aligned 16B chunk -> single LDG.128
            const float4 q = __ldg(tab4 + (i0 >> 1));
            ax = fmaf(w0, q.x, ax);
            ay = fmaf(w0, q.y, ay);
            ax = fmaf(w1, q.z, ax);
            ay = fmaf(w1, q.w, ay);
        } else {
            const float2 e0 = __ldg(tab + i0);
            const float2 e1 = __ldg(tab + i1);
            ax = fmaf(w0, e0.x, ax);
            ay = fmaf(w0, e0.y, ay);
            ax = fmaf(w1, e1.x, ax);
            ay = fmaf(w1, e1.y, ay);
        }
    }
}

__global__ __launch_bounds__(256)
void hash_encode_kernel8(const float* __restrict__ inputs,
                         const float2* __restrict__ emb,
                         float* __restrict__ out,
                         int B)
{
    const int t = blockIdx.x * blockDim.x + threadIdx.x;
    const int point = t >> 3;
    const int slot  = t & 7;
    if (point >= B) return;

    // 8 lanes per point read the same xyz -> warp-broadcast (1-2 lines/warp)
    const float x = __ldg(&inputs[point * 3 + 0]);
    const float y = __ldg(&inputs[point * 3 + 1]);
    const float z = __ldg(&inputs[point * 3 + 2]);

    float a0x, a0y, a1x, a1y;
    encode_level(2 * slot + 0, x, y, z, emb, a0x, a0y);
    encode_level(2 * slot + 1, x, y, z, emb, a1x, a1y);

    // slot s writes floats [4s..4s+3] of the point's 32-float row:
    // warp covers 4 points -> 512B contiguous -> 4 lines per store instr
    float4* __restrict__ dst =
        reinterpret_cast<float4*>(out + (size_t)point * (2 * NLEVELS)) + slot;
    *dst = make_float4(a0x, a0y, a1x, a1y);
}

extern "C" void kernel_launch(void* const* d_in, const int* in_sizes, int n_in,
                              void* d_out, int out_size) {
    const float*  inputs = (const float*)d_in[0];   // [B, 3]
    const float2* emb    = (const float2*)d_in[1];  // [TOTAL_PARAMS, 2]
    float*        out    = (float*)d_out;           // [B, 32]

    const int B = in_sizes[0] / 3;

    init_scales_kernel<<<1, 32>>>();

    const int threads = 256;
    const long long total = (long long)B * 8;
    const int blocks = (int)((total + threads - 1) / threads);
    hash_encode_kernel8<<<blocks, threads>>>(inputs, emb, out, B);
}